// round 7
// baseline (speedup 1.0000x reference)
#include <cuda_runtime.h>
#include <cuda_bf16.h>
#include <cuda_fp16.h>
#include <cstdint>

#define N_NODES 100000
#define N_EDGES 1600000
#define D 128
#define L_LAYERS 3

#define KPAD 272            // bf16 units per weight row (256 data + pad)
#define APAD 48             // bf16 units per A-tile row (32 data + pad)
#define GEMM_TILES ((N_NODES + 127) / 128)   // 782
#define GEMM_GRID 148
#define AGG_BLOCKS 3125     // 32 nodes per block (100000 = 3125*32)

// ---------------- scratch (no allocations allowed) ----------------
__device__ int    g_deg[N_NODES];
__device__ float  g_invdeg[N_NODES];
__device__ int    g_off[N_NODES + 1];
__device__ int    g_cursor[N_NODES];
__device__ int    g_csr[N_EDGES];
__device__ float  g_h0[(size_t)N_NODES * D];
__device__ float  g_h1[(size_t)N_NODES * D];
__device__ float  g_hn[(size_t)N_NODES * D];
__device__ __align__(16) __half g_xf16[(size_t)N_NODES * D];
__device__ __align__(16) __half g_hf16a[(size_t)N_NODES * D];
__device__ __align__(16) __half g_hf16b[(size_t)N_NODES * D];
__device__ int          g_tileflag[GEMM_TILES];
__device__ unsigned int g_tcnt[GEMM_TILES];
// pre-split weights for all 3 layers, permuted-K layout [l][n=128][KPAD]
__device__ __align__(16) __nv_bfloat16 g_wthi[3 * 128 * KPAD];
__device__ __align__(16) __nv_bfloat16 g_wtlo[3 * 128 * KPAD];

// ---------------- CSR build ----------------
__global__ void zero_deg_kernel() {
    int i = blockIdx.x * blockDim.x + threadIdx.x;
    if (i < N_NODES) g_deg[i] = 0;
}

__global__ void count_deg_kernel(const int* __restrict__ dst) {
    int e = blockIdx.x * blockDim.x + threadIdx.x;
    if (e < N_EDGES) atomicAdd(&g_deg[dst[e]], 1);
}

__global__ void scan_offsets_kernel() {
    __shared__ int warp_sums[32];
    __shared__ int carry_sh;
    int t = threadIdx.x, lane = t & 31, w = t >> 5;
    if (t == 0) carry_sh = 0;
    __syncthreads();
    for (int base = 0; base < N_NODES; base += 4096) {
        int i4 = base + t * 4;
        int4 v = make_int4(0, 0, 0, 0);
        if (i4 < N_NODES) v = *(const int4*)&g_deg[i4];
        int s0 = v.x, s1 = s0 + v.y, s2 = s1 + v.z, s3 = s2 + v.w;
        int incl = s3;
        #pragma unroll
        for (int off = 1; off < 32; off <<= 1) {
            int x = __shfl_up_sync(0xffffffffu, incl, off);
            if (lane >= off) incl += x;
        }
        if (lane == 31) warp_sums[w] = incl;
        __syncthreads();
        if (w == 0) {
            int s = warp_sums[lane];
            #pragma unroll
            for (int off = 1; off < 32; off <<= 1) {
                int x = __shfl_up_sync(0xffffffffu, s, off);
                if (lane >= off) s += x;
            }
            warp_sums[lane] = s;
        }
        __syncthreads();
        int carry = carry_sh;
        int woff = (w > 0) ? warp_sums[w - 1] : 0;
        int excl = carry + woff + incl - s3;
        if (i4 < N_NODES) {
            *(int4*)&g_off[i4] =
                make_int4(excl, excl + s0, excl + s1, excl + s2);
            *(float4*)&g_invdeg[i4] = make_float4(
                1.0f / (float)max(v.x, 1), 1.0f / (float)max(v.y, 1),
                1.0f / (float)max(v.z, 1), 1.0f / (float)max(v.w, 1));
            *(int4*)&g_cursor[i4] = make_int4(0, 0, 0, 0);
        }
        __syncthreads();
        if (t == 1023) carry_sh = carry + woff + incl;
        __syncthreads();
    }
    if (t == 0) g_off[N_NODES] = carry_sh;
}

__global__ void fill_csr_kernel(const int* __restrict__ src,
                                const int* __restrict__ dst) {
    int e = blockIdx.x * blockDim.x + threadIdx.x;
    if (e < N_EDGES) {
        int d = dst[e];
        int p = atomicAdd(&g_cursor[d], 1);
        g_csr[g_off[d] + p] = src[e];
    }
}

// ---------------- x -> fp16 copy (once) ----------------
__global__ void convert_x_kernel(const float* __restrict__ x) {
    int i = blockIdx.x * blockDim.x + threadIdx.x;
    if (i < N_NODES * D / 4) {
        float4 v = ((const float4*)x)[i];
        __half2* o = (__half2*)g_xf16;
        o[i * 2]     = __floats2half2_rn(v.x, v.y);
        o[i * 2 + 1] = __floats2half2_rn(v.z, v.w);
    }
}

// ---------------- weight prep, all 3 layers up front ----------------
__global__ void prep_w_kernel(const float* __restrict__ Ws,
                              const float* __restrict__ Wn) {
    int idx = blockIdx.x * blockDim.x + threadIdx.x;
    if (idx >= 3 * 128 * 256) return;
    int l = idx / (128 * 256);
    int rem = idx - l * 128 * 256;
    int n = rem >> 8;
    int k = rem & 255;
    float w = (k < 128) ? __ldg(&Ws[(size_t)l * D * D + k * 128 + n])
                        : __ldg(&Wn[(size_t)l * D * D + (k - 128) * 128 + n]);
    __nv_bfloat16 hi = __float2bfloat16(w);
    __nv_bfloat16 lo = __float2bfloat16(w - __bfloat162float(hi));
    int group = k >> 4, li = k & 15;
    int p = ((li & 7) >> 1) * 4 + (li & 1) + ((li >> 3) << 1);
    int off = l * 128 * KPAD + n * KPAD + group * 16 + p;
    g_wthi[off] = hi;
    g_wtlo[off] = lo;
}

// ---------------- aggregation: tile-aligned blocks, fp16 gather --------------
// Block = 8 warps x 4 nodes = 32 consecutive nodes. After block completes,
// a per-tile counter releases g_tileflag[tile] = tag (4 blocks / tile).
__device__ __forceinline__ void acc_h4(float4& a, uint2 r) {
    __half2 p0 = *reinterpret_cast<__half2*>(&r.x);
    __half2 p1 = *reinterpret_cast<__half2*>(&r.y);
    float2 f0 = __half22float2(p0);
    float2 f1 = __half22float2(p1);
    a.x += f0.x; a.y += f0.y; a.z += f1.x; a.w += f1.y;
}

__global__ void __launch_bounds__(256) aggregate_f16_kernel(
    const __half* __restrict__ hin16, int tag)
{
    int lane = threadIdx.x & 31, warp = threadIdx.x >> 5;
    int node0 = blockIdx.x * 32 + warp * 4;
    const uint2* H = (const uint2*)hin16;   // 4 halves per lane

    #pragma unroll 1
    for (int i = 0; i < 4; i++) {
        int node = node0 + i;               // always < N_NODES (3125*32 exact)
        int s = g_off[node], e = g_off[node + 1];
        float4 a0 = make_float4(0.f, 0.f, 0.f, 0.f);
        float4 a1 = a0, a2 = a0, a3 = a0;
        int j = s;
        for (; j + 4 <= e; j += 4) {
            int u0 = __ldg(&g_csr[j]);
            int u1 = __ldg(&g_csr[j + 1]);
            int u2 = __ldg(&g_csr[j + 2]);
            int u3 = __ldg(&g_csr[j + 3]);
            uint2 r0 = __ldg(&H[(size_t)u0 * 32 + lane]);
            uint2 r1 = __ldg(&H[(size_t)u1 * 32 + lane]);
            uint2 r2 = __ldg(&H[(size_t)u2 * 32 + lane]);
            uint2 r3 = __ldg(&H[(size_t)u3 * 32 + lane]);
            acc_h4(a0, r0); acc_h4(a1, r1); acc_h4(a2, r2); acc_h4(a3, r3);
        }
        for (; j < e; j++) {
            int u = __ldg(&g_csr[j]);
            uint2 r = __ldg(&H[(size_t)u * 32 + lane]);
            acc_h4(a0, r);
        }
        float inv = g_invdeg[node];
        float4 r;
        r.x = (a0.x + a1.x + a2.x + a3.x) * inv;
        r.y = (a0.y + a1.y + a2.y + a3.y) * inv;
        r.z = (a0.z + a1.z + a2.z + a3.z) * inv;
        r.w = (a0.w + a1.w + a2.w + a3.w) * inv;
        ((float4*)g_hn)[(size_t)node * 32 + lane] = r;
    }

    __threadfence();
    __syncthreads();
    if (threadIdx.x == 0) {
        int t = blockIdx.x >> 2;
        unsigned need = (unsigned)min(4, AGG_BLOCKS - (t << 2));
        unsigned old = atomicAdd(&g_tcnt[t], 1u);
        if (((old + 1u) % need) == 0u)
            *(volatile int*)&g_tileflag[t] = tag;
    }
}

// ---------------- persistent bf16-split tensor-core GEMM (8 warps) -----------
//   C = Ahi*Whi + Alo*Whi + Ahi*Wlo  (fp32 accum, m16n8k16 bf16 mma.sync)
// Self half (kc 0-3) from hin; before kc=4 spin on this tile's agg flag.
#define ABUF_SMEM (2 * 128 * APAD)
#define GEMM_SMEM_BYTES ((2 * 128 * KPAD + 2 * ABUF_SMEM) * 2)   // 188416

__device__ __forceinline__ void mma_bf16(float c[4], uint32_t a0, uint32_t a1,
                                         uint32_t a2, uint32_t a3,
                                         uint32_t b0, uint32_t b1) {
    asm volatile(
        "mma.sync.aligned.m16n8k16.row.col.f32.bf16.bf16.f32 "
        "{%0,%1,%2,%3}, {%4,%5,%6,%7}, {%8,%9}, {%0,%1,%2,%3};"
        : "+f"(c[0]), "+f"(c[1]), "+f"(c[2]), "+f"(c[3])
        : "r"(a0), "r"(a1), "r"(a2), "r"(a3), "r"(b0), "r"(b1));
}

__global__ void __launch_bounds__(256, 1) sage_gemm_kernel(
    const float* __restrict__ hin,
    const __nv_bfloat16* __restrict__ wthi,
    const __nv_bfloat16* __restrict__ wtlo,
    const float* __restrict__ bias, float* __restrict__ out,
    __half* __restrict__ out16, int tag)
{
    extern __shared__ __align__(16) __nv_bfloat16 smem[];
    __nv_bfloat16* sWhi = smem;                       // [128][KPAD]
    __nv_bfloat16* sWlo = sWhi + 128 * KPAD;
    __nv_bfloat16* sAbuf = sWlo + 128 * KPAD;         // 2 x (hi | lo)

    int tid = threadIdx.x;
    int lane = tid & 31, warp = tid >> 5;
    int warpM = warp & 3, warpN = warp >> 2;          // 4 x 2 warp grid
    int g = lane >> 2, tig = lane & 3;
    const float* hn = g_hn;

    // stage pre-split weights once per SM
    {
        const uint4* s0 = (const uint4*)wthi;
        const uint4* s1 = (const uint4*)wtlo;
        uint4* d0 = (uint4*)sWhi;
        uint4* d1 = (uint4*)sWlo;
        for (int i = tid; i < (128 * KPAD) / 8; i += 256) {
            d0[i] = s0[i];
            d1[i] = s1[i];
        }
    }

    float bx[8], by[8];
    #pragma unroll
    for (int nf = 0; nf < 8; nf++) {
        int col = warpN * 64 + nf * 8 + tig * 2;
        bx[nf] = __ldg(&bias[col]);
        by[nf] = __ldg(&bias[col + 1]);
    }

    const int ptab[4] = {0, 8, 2, 10};

    for (int tile = blockIdx.x; tile < GEMM_TILES; tile += gridDim.x) {
        int m0 = tile * 128;

        float acc[2][8][4];
        #pragma unroll
        for (int mf = 0; mf < 2; mf++)
            #pragma unroll
            for (int nf = 0; nf < 8; nf++)
                #pragma unroll
                for (int r = 0; r < 4; r++) acc[mf][nf][r] = 0.f;

        float4 pref[4];
        #pragma unroll
        for (int i = 0; i < 4; i++) {
            int idx = tid + 256 * i;
            int r = idx >> 3, c4 = idx & 7;
            int m = m0 + r;
            pref[i] = make_float4(0.f, 0.f, 0.f, 0.f);
            if (m < N_NODES)
                pref[i] = __ldg((const float4*)(hin + (size_t)m * D + c4 * 4));
        }

        #pragma unroll 1
        for (int kc = 0; kc < 8; kc++) {
            __nv_bfloat16* sAhi = sAbuf + (kc & 1) * ABUF_SMEM;
            __nv_bfloat16* sAlo = sAhi + 128 * APAD;

            #pragma unroll
            for (int i = 0; i < 4; i++) {
                int idx = tid + 256 * i;
                int r = idx >> 3, c4 = idx & 7;
                float4 v = pref[i];
                __nv_bfloat16 hx = __float2bfloat16(v.x);
                __nv_bfloat16 hy = __float2bfloat16(v.y);
                __nv_bfloat16 hz = __float2bfloat16(v.z);
                __nv_bfloat16 hw = __float2bfloat16(v.w);
                __nv_bfloat16 lx = __float2bfloat16(v.x - __bfloat162float(hx));
                __nv_bfloat16 ly = __float2bfloat16(v.y - __bfloat162float(hy));
                __nv_bfloat16 lz = __float2bfloat16(v.z - __bfloat162float(hz));
                __nv_bfloat16 lw = __float2bfloat16(v.w - __bfloat162float(hw));
                uint32_t hp0 = ((uint32_t)__bfloat16_as_ushort(hy) << 16) |
                               __bfloat16_as_ushort(hx);
                uint32_t hp1 = ((uint32_t)__bfloat16_as_ushort(hw) << 16) |
                               __bfloat16_as_ushort(hz);
                uint32_t lp0 = ((uint32_t)__bfloat16_as_ushort(ly) << 16) |
                               __bfloat16_as_ushort(lx);
                uint32_t lp1 = ((uint32_t)__bfloat16_as_ushort(lw) << 16) |
                               __bfloat16_as_ushort(lz);
                int group = c4 >> 2;
                int p0 = ptab[c4 & 3];
                int base = r * APAD + group * 16;
                uint32_t* AH = (uint32_t*)sAhi;
                uint32_t* AL = (uint32_t*)sAlo;
                AH[(base + p0) >> 1]     = hp0;
                AH[(base + p0 + 4) >> 1] = hp1;
                AL[(base + p0) >> 1]     = lp0;
                AL[(base + p0 + 4) >> 1] = lp1;
            }
            __syncthreads();   // first iteration also covers W staging

            if (kc < 7) {
                int nkc = kc + 1;
                if (nkc == 4) {   // entering neighbor half: wait for agg of tile
                    volatile int* f = &g_tileflag[tile];
                    while (*f != tag) __nanosleep(128);
                    __threadfence();
                }
                const float* srcp = (nkc < 4) ? hin : hn;
                int koff = (nkc & 3) * 32;
                #pragma unroll
                for (int i = 0; i < 4; i++) {
                    int idx = tid + 256 * i;
                    int r = idx >> 3, c4 = idx & 7;
                    int m = m0 + r;
                    pref[i] = make_float4(0.f, 0.f, 0.f, 0.f);
                    if (m < N_NODES)
                        pref[i] = __ldg((const float4*)(srcp + (size_t)m * D +
                                                        koff + c4 * 4));
                }
            }

            #pragma unroll
            for (int ks = 0; ks < 2; ks++) {
                int ka = ks * 16;
                int kw = kc * 32 + ks * 16;
                uint32_t Ah[2][4], Al[2][4];
                #pragma unroll
                for (int mf = 0; mf < 2; mf++) {
                    int r0 = warpM * 32 + mf * 16;
                    uint2 t0 = *(const uint2*)&sAhi[(r0 + g) * APAD + ka + tig * 4];
                    uint2 t1 = *(const uint2*)&sAhi[(r0 + g + 8) * APAD + ka + tig * 4];
                    Ah[mf][0] = t0.x; Ah[mf][1] = t1.x; Ah[mf][2] = t0.y; Ah[mf][3] = t1.y;
                    uint2 u0 = *(const uint2*)&sAlo[(r0 + g) * APAD + ka + tig * 4];
                    uint2 u1 = *(const uint2*)&sAlo[(r0 + g + 8) * APAD + ka + tig * 4];
                    Al[mf][0] = u0.x; Al[mf][1] = u1.x; Al[mf][2] = u0.y; Al[mf][3] = u1.y;
                }
                #pragma unroll
                for (int nf = 0; nf < 8; nf++) {
                    int nr = warpN * 64 + nf * 8 + g;
                    uint2 bh = *(const uint2*)&sWhi[nr * KPAD + kw + tig * 4];
                    uint2 bl = *(const uint2*)&sWlo[nr * KPAD + kw + tig * 4];
                    #pragma unroll
                    for (int mf = 0; mf < 2; mf++) {
                        mma_bf16(acc[mf][nf], Ah[mf][0], Ah[mf][1], Ah[mf][2], Ah[mf][3], bh.x, bh.y);
                        mma_bf16(acc[mf][nf], Al[mf][0], Al[mf][1], Al[mf][2], Al[mf][3], bh.x, bh.y);
                        mma_bf16(acc[mf][nf], Ah[mf][0], Ah[mf][1], Ah[mf][2], Ah[mf][3], bl.x, bl.y);
                    }
                }
            }
        }

        // epilogue: + bias, relu, store fp32 + fp16 copy
        #pragma unroll
        for (int mf = 0; mf < 2; mf++) {
            #pragma unroll
            for (int nf = 0; nf < 8; nf++) {
                int row0 = m0 + warpM * 32 + mf * 16 + g;
                int col = warpN * 64 + nf * 8 + tig * 2;
                if (row0 < N_NODES) {
                    float r0 = acc[mf][nf][0] + bx[nf]; r0 = r0 > 0.f ? r0 : 0.f;
                    float r1 = acc[mf][nf][1] + by[nf]; r1 = r1 > 0.f ? r1 : 0.f;
                    *(float2*)&out[(size_t)row0 * D + col] = make_float2(r0, r1);
                    *(__half2*)&out16[(size_t)row0 * D + col] = __floats2half2_rn(r0, r1);
                }
                if (row0 + 8 < N_NODES) {
                    float r2 = acc[mf][nf][2] + bx[nf]; r2 = r2 > 0.f ? r2 : 0.f;
                    float r3 = acc[mf][nf][3] + by[nf]; r3 = r3 > 0.f ? r3 : 0.f;
                    *(float2*)&out[(size_t)(row0 + 8) * D + col] = make_float2(r2, r3);
                    *(__half2*)&out16[(size_t)(row0 + 8) * D + col] = __floats2half2_rn(r2, r3);
                }
            }
        }
    }
}

// ---------------- launch ----------------
extern "C" void kernel_launch(void* const* d_in, const int* in_sizes, int n_in,
                              void* d_out, int out_size)
{
    const float* x       = (const float*)d_in[0];
    const float* W_self  = (const float*)d_in[1];
    const float* W_neigh = (const float*)d_in[2];
    const float* bias    = (const float*)d_in[3];
    const int*   src     = (const int*)d_in[4];
    const int*   dst     = (const int*)d_in[5];
    float* out = (float*)d_out;

    void *p0, *p1, *px16, *pa16, *pb16, *pwh, *pwl;
    cudaGetSymbolAddress(&p0, g_h0);
    cudaGetSymbolAddress(&p1, g_h1);
    cudaGetSymbolAddress(&px16, g_xf16);
    cudaGetSymbolAddress(&pa16, g_hf16a);
    cudaGetSymbolAddress(&pb16, g_hf16b);
    cudaGetSymbolAddress(&pwh, g_wthi);
    cudaGetSymbolAddress(&pwl, g_wtlo);
    float* h0 = (float*)p0;
    float* h1 = (float*)p1;
    __half* x16 = (__half*)px16;
    __half* a16 = (__half*)pa16;
    __half* b16 = (__half*)pb16;
    const __nv_bfloat16* wthi = (const __nv_bfloat16*)pwh;
    const __nv_bfloat16* wtlo = (const __nv_bfloat16*)pwl;

    // side stream + events: created once on the first (non-captured) call;
    // identical GPU work is issued on every call.
    static cudaStream_t s2 = nullptr;
    static cudaEvent_t evFork, evCSR, evPrep, evL0, evL1, evL2, evEnd;
    if (s2 == nullptr) {
        cudaStreamCreateWithFlags(&s2, cudaStreamNonBlocking);
        cudaEventCreateWithFlags(&evFork, cudaEventDisableTiming);
        cudaEventCreateWithFlags(&evCSR, cudaEventDisableTiming);
        cudaEventCreateWithFlags(&evPrep, cudaEventDisableTiming);
        cudaEventCreateWithFlags(&evL0, cudaEventDisableTiming);
        cudaEventCreateWithFlags(&evL1, cudaEventDisableTiming);
        cudaEventCreateWithFlags(&evL2, cudaEventDisableTiming);
        cudaEventCreateWithFlags(&evEnd, cudaEventDisableTiming);
        cudaFuncSetAttribute(sage_gemm_kernel,
                             cudaFuncAttributeMaxDynamicSharedMemorySize,
                             GEMM_SMEM_BYTES);
    }
    cudaEvent_t evL[3] = {evL0, evL1, evL2};

    // fork: s2 does fp16 convert + all-layer weight prep
    cudaEventRecord(evFork, 0);
    cudaStreamWaitEvent(s2, evFork, 0);
    convert_x_kernel<<<(N_NODES * D / 4 + 255) / 256, 256, 0, s2>>>(x);
    prep_w_kernel<<<(3 * 128 * 256 + 255) / 256, 256, 0, s2>>>(W_self, W_neigh);
    cudaEventRecord(evPrep, s2);

    // main stream: CSR build
    zero_deg_kernel<<<(N_NODES + 255) / 256, 256>>>();
    count_deg_kernel<<<(N_EDGES + 255) / 256, 256>>>(dst);
    scan_offsets_kernel<<<1, 1024>>>();
    fill_csr_kernel<<<(N_EDGES + 255) / 256, 256>>>(src, dst);
    cudaEventRecord(evCSR, 0);
    cudaStreamWaitEvent(s2, evCSR, 0);    // agg needs CSR
    cudaStreamWaitEvent(0, evPrep, 0);    // gemm needs weights

    const float* hin32 = x;
    const __half* hin16 = x16;
    float* houts32[3] = {h0, h1, out};
    __half* houts16[3] = {a16, b16, a16};
    for (int l = 0; l < L_LAYERS; l++) {
        // aggregation on s2, GEMM on main stream; GEMM self-half overlaps agg,
        // neighbor-half gated per-tile by g_tileflag (tag = l+1).
        aggregate_f16_kernel<<<AGG_BLOCKS, 256, 0, s2>>>(hin16, l + 1);
        sage_gemm_kernel<<<GEMM_GRID, 256, GEMM_SMEM_BYTES>>>(
            hin32, wthi + (size_t)l * 128 * KPAD, wtlo + (size_t)l * 128 * KPAD,
            bias + (size_t)l * D, houts32[l], houts16[l], l + 1);
        cudaEventRecord(evL[l], 0);
        cudaStreamWaitEvent(s2, evL[l], 0);   // next agg waits this gemm
        hin32 = houts32[l];
        hin16 = houts16[l];
    }
    cudaEventRecord(evEnd, s2);
    cudaStreamWaitEvent(0, evEnd, 0);         // join fork before capture ends
}

// round 8
// speedup vs baseline: 1.0267x; 1.0267x over previous
#include <cuda_runtime.h>
#include <cuda_bf16.h>
#include <cuda_fp16.h>
#include <cstdint>

#define N_NODES 100000
#define N_EDGES 1600000
#define D 128
#define L_LAYERS 3

#define KPAD 272            // bf16 units per weight row (256 data + pad)
#define APAD 48             // bf16 units per A-tile row (32 data + pad)
#define GEMM_TILES ((N_NODES + 127) / 128)   // 782
#define GEMM_GRID 148

// ---------------- scratch (no allocations allowed) ----------------
__device__ int    g_deg[N_NODES];
__device__ float  g_invdeg[N_NODES];
__device__ int    g_off[N_NODES + 1];
__device__ int    g_cursor[N_NODES];
__device__ int    g_csr[N_EDGES];
__device__ float  g_h0[(size_t)N_NODES * D];
__device__ float  g_h1[(size_t)N_NODES * D];
__device__ float  g_hn[(size_t)N_NODES * D];
__device__ __align__(16) __half g_xf16[(size_t)N_NODES * D];
__device__ __align__(16) __half g_hf16a[(size_t)N_NODES * D];
__device__ __align__(16) __half g_hf16b[(size_t)N_NODES * D];
// pre-split weights for all 3 layers, permuted-K layout [l][n=128][KPAD]
__device__ __align__(16) __nv_bfloat16 g_wthi[3 * 128 * KPAD];
__device__ __align__(16) __nv_bfloat16 g_wtlo[3 * 128 * KPAD];

// ---------------- CSR build ----------------
__global__ void zero_deg_kernel() {
    int i = blockIdx.x * blockDim.x + threadIdx.x;
    if (i < N_NODES) g_deg[i] = 0;
}

__global__ void count_deg_kernel(const int* __restrict__ dst) {
    int e = blockIdx.x * blockDim.x + threadIdx.x;
    if (e < N_EDGES) atomicAdd(&g_deg[dst[e]], 1);
}

__global__ void scan_offsets_kernel() {
    __shared__ int warp_sums[32];
    __shared__ int carry_sh;
    int t = threadIdx.x, lane = t & 31, w = t >> 5;
    if (t == 0) carry_sh = 0;
    __syncthreads();
    for (int base = 0; base < N_NODES; base += 4096) {
        int i4 = base + t * 4;
        int4 v = make_int4(0, 0, 0, 0);
        if (i4 < N_NODES) v = *(const int4*)&g_deg[i4];
        int s0 = v.x, s1 = s0 + v.y, s2 = s1 + v.z, s3 = s2 + v.w;
        int incl = s3;
        #pragma unroll
        for (int off = 1; off < 32; off <<= 1) {
            int x = __shfl_up_sync(0xffffffffu, incl, off);
            if (lane >= off) incl += x;
        }
        if (lane == 31) warp_sums[w] = incl;
        __syncthreads();
        if (w == 0) {
            int s = warp_sums[lane];
            #pragma unroll
            for (int off = 1; off < 32; off <<= 1) {
                int x = __shfl_up_sync(0xffffffffu, s, off);
                if (lane >= off) s += x;
            }
            warp_sums[lane] = s;
        }
        __syncthreads();
        int carry = carry_sh;
        int woff = (w > 0) ? warp_sums[w - 1] : 0;
        int excl = carry + woff + incl - s3;
        if (i4 < N_NODES) {
            *(int4*)&g_off[i4] =
                make_int4(excl, excl + s0, excl + s1, excl + s2);
            *(float4*)&g_invdeg[i4] = make_float4(
                1.0f / (float)max(v.x, 1), 1.0f / (float)max(v.y, 1),
                1.0f / (float)max(v.z, 1), 1.0f / (float)max(v.w, 1));
            *(int4*)&g_cursor[i4] = make_int4(0, 0, 0, 0);
        }
        __syncthreads();
        if (t == 1023) carry_sh = carry + woff + incl;
        __syncthreads();
    }
    if (t == 0) g_off[N_NODES] = carry_sh;
}

__global__ void fill_csr_kernel(const int* __restrict__ src,
                                const int* __restrict__ dst) {
    int e = blockIdx.x * blockDim.x + threadIdx.x;
    if (e < N_EDGES) {
        int d = dst[e];
        int p = atomicAdd(&g_cursor[d], 1);
        g_csr[g_off[d] + p] = src[e];
    }
}

// ---------------- x -> fp16 copy (once) ----------------
__global__ void convert_x_kernel(const float* __restrict__ x) {
    int i = blockIdx.x * blockDim.x + threadIdx.x;
    if (i < N_NODES * D / 4) {
        float4 v = ((const float4*)x)[i];
        __half2* o = (__half2*)g_xf16;
        o[i * 2]     = __floats2half2_rn(v.x, v.y);
        o[i * 2 + 1] = __floats2half2_rn(v.z, v.w);
    }
}

// ---------------- weight prep, all 3 layers up front ----------------
__global__ void prep_w_kernel(const float* __restrict__ Ws,
                              const float* __restrict__ Wn) {
    int idx = blockIdx.x * blockDim.x + threadIdx.x;
    if (idx >= 3 * 128 * 256) return;
    int l = idx / (128 * 256);
    int rem = idx - l * 128 * 256;
    int n = rem >> 8;
    int k = rem & 255;
    float w = (k < 128) ? __ldg(&Ws[(size_t)l * D * D + k * 128 + n])
                        : __ldg(&Wn[(size_t)l * D * D + (k - 128) * 128 + n]);
    __nv_bfloat16 hi = __float2bfloat16(w);
    __nv_bfloat16 lo = __float2bfloat16(w - __bfloat162float(hi));
    int group = k >> 4, li = k & 15;
    int p = ((li & 7) >> 1) * 4 + (li & 1) + ((li >> 3) << 1);
    int off = l * 128 * KPAD + n * KPAD + group * 16 + p;
    g_wthi[off] = hi;
    g_wtlo[off] = lo;
}

// ---------------- aggregation: one warp per node, fp16 gather ----------------
__device__ __forceinline__ void acc_h4(float4& a, uint2 r) {
    __half2 p0 = *reinterpret_cast<__half2*>(&r.x);
    __half2 p1 = *reinterpret_cast<__half2*>(&r.y);
    float2 f0 = __half22float2(p0);
    float2 f1 = __half22float2(p1);
    a.x += f0.x; a.y += f0.y; a.z += f1.x; a.w += f1.y;
}

__global__ void __launch_bounds__(256) aggregate_f16_kernel(
    const __half* __restrict__ hin16)
{
    int gw = (blockIdx.x * blockDim.x + threadIdx.x) >> 5;
    int lane = threadIdx.x & 31;
    if (gw >= N_NODES) return;
    int s = g_off[gw], e = g_off[gw + 1];
    const uint2* H = (const uint2*)hin16;   // 4 halves per lane
    float4 a0 = make_float4(0.f, 0.f, 0.f, 0.f);
    float4 a1 = a0, a2 = a0, a3 = a0;
    int j = s;
    for (; j + 4 <= e; j += 4) {
        int u0 = __ldg(&g_csr[j]);
        int u1 = __ldg(&g_csr[j + 1]);
        int u2 = __ldg(&g_csr[j + 2]);
        int u3 = __ldg(&g_csr[j + 3]);
        uint2 r0 = __ldg(&H[(size_t)u0 * 32 + lane]);
        uint2 r1 = __ldg(&H[(size_t)u1 * 32 + lane]);
        uint2 r2 = __ldg(&H[(size_t)u2 * 32 + lane]);
        uint2 r3 = __ldg(&H[(size_t)u3 * 32 + lane]);
        acc_h4(a0, r0); acc_h4(a1, r1); acc_h4(a2, r2); acc_h4(a3, r3);
    }
    for (; j < e; j++) {
        int u = __ldg(&g_csr[j]);
        uint2 r = __ldg(&H[(size_t)u * 32 + lane]);
        acc_h4(a0, r);
    }
    float inv = g_invdeg[gw];
    float4 r;
    r.x = (a0.x + a1.x + a2.x + a3.x) * inv;
    r.y = (a0.y + a1.y + a2.y + a3.y) * inv;
    r.z = (a0.z + a1.z + a2.z + a3.z) * inv;
    r.w = (a0.w + a1.w + a2.w + a3.w) * inv;
    ((float4*)g_hn)[(size_t)gw * 32 + lane] = r;
}

// ---------------- persistent bf16-split tensor-core GEMM (8 warps) -----------
//   C = Ahi*Whi + Alo*Whi + Ahi*Wlo  (fp32 accum, m16n8k16 bf16 mma.sync)
#define ABUF_SMEM (2 * 128 * APAD)
#define GEMM_SMEM_BYTES ((2 * 128 * KPAD + 2 * ABUF_SMEM) * 2)   // 188416

__device__ __forceinline__ void mma_bf16(float c[4], uint32_t a0, uint32_t a1,
                                         uint32_t a2, uint32_t a3,
                                         uint32_t b0, uint32_t b1) {
    asm volatile(
        "mma.sync.aligned.m16n8k16.row.col.f32.bf16.bf16.f32 "
        "{%0,%1,%2,%3}, {%4,%5,%6,%7}, {%8,%9}, {%0,%1,%2,%3};"
        : "+f"(c[0]), "+f"(c[1]), "+f"(c[2]), "+f"(c[3])
        : "r"(a0), "r"(a1), "r"(a2), "r"(a3), "r"(b0), "r"(b1));
}

__global__ void __launch_bounds__(256, 1) sage_gemm_kernel(
    const float* __restrict__ hin,
    const __nv_bfloat16* __restrict__ wthi,
    const __nv_bfloat16* __restrict__ wtlo,
    const float* __restrict__ bias, float* __restrict__ out,
    __half* __restrict__ out16)
{
    extern __shared__ __align__(16) __nv_bfloat16 smem[];
    __nv_bfloat16* sWhi = smem;                       // [128][KPAD]
    __nv_bfloat16* sWlo = sWhi + 128 * KPAD;
    __nv_bfloat16* sAbuf = sWlo + 128 * KPAD;         // 2 x (hi | lo)

    int tid = threadIdx.x;
    int lane = tid & 31, warp = tid >> 5;
    int warpM = warp & 3, warpN = warp >> 2;          // 4 x 2 warp grid
    int g = lane >> 2, tig = lane & 3;
    const float* hn = g_hn;

    // stage pre-split weights once per SM
    {
        const uint4* s0 = (const uint4*)wthi;
        const uint4* s1 = (const uint4*)wtlo;
        uint4* d0 = (uint4*)sWhi;
        uint4* d1 = (uint4*)sWlo;
        for (int i = tid; i < (128 * KPAD) / 8; i += 256) {
            d0[i] = s0[i];
            d1[i] = s1[i];
        }
    }

    float bx[8], by[8];
    #pragma unroll
    for (int nf = 0; nf < 8; nf++) {
        int col = warpN * 64 + nf * 8 + tig * 2;
        bx[nf] = __ldg(&bias[col]);
        by[nf] = __ldg(&bias[col + 1]);
    }

    const int ptab[4] = {0, 8, 2, 10};

    for (int tile = blockIdx.x; tile < GEMM_TILES; tile += gridDim.x) {
        int m0 = tile * 128;

        float acc[2][8][4];
        #pragma unroll
        for (int mf = 0; mf < 2; mf++)
            #pragma unroll
            for (int nf = 0; nf < 8; nf++)
                #pragma unroll
                for (int r = 0; r < 4; r++) acc[mf][nf][r] = 0.f;

        float4 pref[4];
        #pragma unroll
        for (int i = 0; i < 4; i++) {
            int idx = tid + 256 * i;
            int r = idx >> 3, c4 = idx & 7;
            int m = m0 + r;
            pref[i] = make_float4(0.f, 0.f, 0.f, 0.f);
            if (m < N_NODES)
                pref[i] = __ldg((const float4*)(hin + (size_t)m * D + c4 * 4));
        }

        #pragma unroll 1
        for (int kc = 0; kc < 8; kc++) {
            __nv_bfloat16* sAhi = sAbuf + (kc & 1) * ABUF_SMEM;
            __nv_bfloat16* sAlo = sAhi + 128 * APAD;

            #pragma unroll
            for (int i = 0; i < 4; i++) {
                int idx = tid + 256 * i;
                int r = idx >> 3, c4 = idx & 7;
                float4 v = pref[i];
                __nv_bfloat16 hx = __float2bfloat16(v.x);
                __nv_bfloat16 hy = __float2bfloat16(v.y);
                __nv_bfloat16 hz = __float2bfloat16(v.z);
                __nv_bfloat16 hw = __float2bfloat16(v.w);
                __nv_bfloat16 lx = __float2bfloat16(v.x - __bfloat162float(hx));
                __nv_bfloat16 ly = __float2bfloat16(v.y - __bfloat162float(hy));
                __nv_bfloat16 lz = __float2bfloat16(v.z - __bfloat162float(hz));
                __nv_bfloat16 lw = __float2bfloat16(v.w - __bfloat162float(hw));
                uint32_t hp0 = ((uint32_t)__bfloat16_as_ushort(hy) << 16) |
                               __bfloat16_as_ushort(hx);
                uint32_t hp1 = ((uint32_t)__bfloat16_as_ushort(hw) << 16) |
                               __bfloat16_as_ushort(hz);
                uint32_t lp0 = ((uint32_t)__bfloat16_as_ushort(ly) << 16) |
                               __bfloat16_as_ushort(lx);
                uint32_t lp1 = ((uint32_t)__bfloat16_as_ushort(lw) << 16) |
                               __bfloat16_as_ushort(lz);
                int group = c4 >> 2;
                int p0 = ptab[c4 & 3];
                int base = r * APAD + group * 16;
                uint32_t* AH = (uint32_t*)sAhi;
                uint32_t* AL = (uint32_t*)sAlo;
                AH[(base + p0) >> 1]     = hp0;
                AH[(base + p0 + 4) >> 1] = hp1;
                AL[(base + p0) >> 1]     = lp0;
                AL[(base + p0 + 4) >> 1] = lp1;
            }
            __syncthreads();   // first iteration also covers W staging

            if (kc < 7) {
                int nkc = kc + 1;
                const float* srcp = (nkc < 4) ? hin : hn;
                int koff = (nkc & 3) * 32;
                #pragma unroll
                for (int i = 0; i < 4; i++) {
                    int idx = tid + 256 * i;
                    int r = idx >> 3, c4 = idx & 7;
                    int m = m0 + r;
                    pref[i] = make_float4(0.f, 0.f, 0.f, 0.f);
                    if (m < N_NODES)
                        pref[i] = __ldg((const float4*)(srcp + (size_t)m * D +
                                                        koff + c4 * 4));
                }
            }

            #pragma unroll
            for (int ks = 0; ks < 2; ks++) {
                int ka = ks * 16;
                int kw = kc * 32 + ks * 16;
                uint32_t Ah[2][4], Al[2][4];
                #pragma unroll
                for (int mf = 0; mf < 2; mf++) {
                    int r0 = warpM * 32 + mf * 16;
                    uint2 t0 = *(const uint2*)&sAhi[(r0 + g) * APAD + ka + tig * 4];
                    uint2 t1 = *(const uint2*)&sAhi[(r0 + g + 8) * APAD + ka + tig * 4];
                    Ah[mf][0] = t0.x; Ah[mf][1] = t1.x; Ah[mf][2] = t0.y; Ah[mf][3] = t1.y;
                    uint2 u0 = *(const uint2*)&sAlo[(r0 + g) * APAD + ka + tig * 4];
                    uint2 u1 = *(const uint2*)&sAlo[(r0 + g + 8) * APAD + ka + tig * 4];
                    Al[mf][0] = u0.x; Al[mf][1] = u1.x; Al[mf][2] = u0.y; Al[mf][3] = u1.y;
                }
                #pragma unroll
                for (int nf = 0; nf < 8; nf++) {
                    int nr = warpN * 64 + nf * 8 + g;
                    uint2 bh = *(const uint2*)&sWhi[nr * KPAD + kw + tig * 4];
                    uint2 bl = *(const uint2*)&sWlo[nr * KPAD + kw + tig * 4];
                    #pragma unroll
                    for (int mf = 0; mf < 2; mf++) {
                        mma_bf16(acc[mf][nf], Ah[mf][0], Ah[mf][1], Ah[mf][2], Ah[mf][3], bh.x, bh.y);
                        mma_bf16(acc[mf][nf], Al[mf][0], Al[mf][1], Al[mf][2], Al[mf][3], bh.x, bh.y);
                        mma_bf16(acc[mf][nf], Ah[mf][0], Ah[mf][1], Ah[mf][2], Ah[mf][3], bl.x, bl.y);
                    }
                }
            }
        }

        // epilogue: + bias, relu, store fp32 + fp16 copy
        #pragma unroll
        for (int mf = 0; mf < 2; mf++) {
            #pragma unroll
            for (int nf = 0; nf < 8; nf++) {
                int row0 = m0 + warpM * 32 + mf * 16 + g;
                int col = warpN * 64 + nf * 8 + tig * 2;
                if (row0 < N_NODES) {
                    float r0 = acc[mf][nf][0] + bx[nf]; r0 = r0 > 0.f ? r0 : 0.f;
                    float r1 = acc[mf][nf][1] + by[nf]; r1 = r1 > 0.f ? r1 : 0.f;
                    *(float2*)&out[(size_t)row0 * D + col] = make_float2(r0, r1);
                    *(__half2*)&out16[(size_t)row0 * D + col] = __floats2half2_rn(r0, r1);
                }
                if (row0 + 8 < N_NODES) {
                    float r2 = acc[mf][nf][2] + bx[nf]; r2 = r2 > 0.f ? r2 : 0.f;
                    float r3 = acc[mf][nf][3] + by[nf]; r3 = r3 > 0.f ? r3 : 0.f;
                    *(float2*)&out[(size_t)(row0 + 8) * D + col] = make_float2(r2, r3);
                    *(__half2*)&out16[(size_t)(row0 + 8) * D + col] = __floats2half2_rn(r2, r3);
                }
            }
        }
    }
}

// ---------------- launch ----------------
extern "C" void kernel_launch(void* const* d_in, const int* in_sizes, int n_in,
                              void* d_out, int out_size)
{
    const float* x       = (const float*)d_in[0];
    const float* W_self  = (const float*)d_in[1];
    const float* W_neigh = (const float*)d_in[2];
    const float* bias    = (const float*)d_in[3];
    const int*   src     = (const int*)d_in[4];
    const int*   dst     = (const int*)d_in[5];
    float* out = (float*)d_out;

    void *p0, *p1, *px16, *pa16, *pb16, *pwh, *pwl;
    cudaGetSymbolAddress(&p0, g_h0);
    cudaGetSymbolAddress(&p1, g_h1);
    cudaGetSymbolAddress(&px16, g_xf16);
    cudaGetSymbolAddress(&pa16, g_hf16a);
    cudaGetSymbolAddress(&pb16, g_hf16b);
    cudaGetSymbolAddress(&pwh, g_wthi);
    cudaGetSymbolAddress(&pwl, g_wtlo);
    float* h0 = (float*)p0;
    float* h1 = (float*)p1;
    __half* x16 = (__half*)px16;
    __half* a16 = (__half*)pa16;
    __half* b16 = (__half*)pb16;
    const __nv_bfloat16* wthi = (const __nv_bfloat16*)pwh;
    const __nv_bfloat16* wtlo = (const __nv_bfloat16*)pwl;

    // side stream + events for setup-only fork (created once, first call is
    // outside graph capture; identical work issued every call).
    static cudaStream_t s2 = nullptr;
    static cudaEvent_t evFork, evPrep;
    if (s2 == nullptr) {
        cudaStreamCreateWithFlags(&s2, cudaStreamNonBlocking);
        cudaEventCreateWithFlags(&evFork, cudaEventDisableTiming);
        cudaEventCreateWithFlags(&evPrep, cudaEventDisableTiming);
        cudaFuncSetAttribute(sage_gemm_kernel,
                             cudaFuncAttributeMaxDynamicSharedMemorySize,
                             GEMM_SMEM_BYTES);
    }

    // fork: convert x -> fp16 and pre-split all weights, concurrent with CSR
    cudaEventRecord(evFork, 0);
    cudaStreamWaitEvent(s2, evFork, 0);
    convert_x_kernel<<<(N_NODES * D / 4 + 255) / 256, 256, 0, s2>>>(x);
    prep_w_kernel<<<(3 * 128 * 256 + 255) / 256, 256, 0, s2>>>(W_self, W_neigh);
    cudaEventRecord(evPrep, s2);

    // main stream: CSR build
    zero_deg_kernel<<<(N_NODES + 255) / 256, 256>>>();
    count_deg_kernel<<<(N_EDGES + 255) / 256, 256>>>(dst);
    scan_offsets_kernel<<<1, 1024>>>();
    fill_csr_kernel<<<(N_EDGES + 255) / 256, 256>>>(src, dst);
    cudaStreamWaitEvent(0, evPrep, 0);    // join: agg needs x16, gemm needs W

    const float* hin32 = x;
    const __half* hin16 = x16;
    float* houts32[3] = {h0, h1, out};
    __half* houts16[3] = {a16, b16, a16};
    for (int l = 0; l < L_LAYERS; l++) {
        aggregate_f16_kernel<<<(N_NODES + 7) / 8, 256>>>(hin16);
        sage_gemm_kernel<<<GEMM_GRID, 256, GEMM_SMEM_BYTES>>>(
            hin32, wthi + (size_t)l * 128 * KPAD, wtlo + (size_t)l * 128 * KPAD,
            bias + (size_t)l * D, houts32[l], houts16[l]);
        hin32 = houts32[l];
        hin16 = houts16[l];
    }
}

// round 9
// speedup vs baseline: 1.4891x; 1.4504x over previous
#include <cuda_runtime.h>
#include <cuda_fp16.h>
#include <cstdint>

#define N_NODES 100000
#define N_EDGES 1600000
#define D 128
#define L_LAYERS 3

#define KPAD 264            // fp16 units per weight row (256 data + 8 pad)
#define APAD 40             // fp16 units per A-tile row (32 data + 8 pad)
#define GEMM_TILES ((N_NODES + 127) / 128)   // 782
#define GEMM_GRID 296       // 2 CTAs per SM

// ---------------- scratch (no allocations allowed) ----------------
__device__ int    g_deg[N_NODES];
__device__ float  g_invdeg[N_NODES];
__device__ int    g_off[N_NODES + 1];
__device__ int    g_cursor[N_NODES];
__device__ int    g_csr[N_EDGES];
__device__ __align__(16) __half g_xf16[(size_t)N_NODES * D];
__device__ __align__(16) __half g_hf16a[(size_t)N_NODES * D];
__device__ __align__(16) __half g_hf16b[(size_t)N_NODES * D];
__device__ __align__(16) __half g_hn16[(size_t)N_NODES * D];
// fp16 weights, all 3 layers, transposed + permuted-K layout [l][n=128][KPAD]
__device__ __align__(16) __half g_wt16[3 * 128 * KPAD];

// ---------------- CSR build ----------------
__global__ void zero_deg_kernel() {
    int i = blockIdx.x * blockDim.x + threadIdx.x;
    if (i < N_NODES) g_deg[i] = 0;
}

__global__ void count_deg_kernel(const int* __restrict__ dst) {
    int e = blockIdx.x * blockDim.x + threadIdx.x;
    if (e < N_EDGES) atomicAdd(&g_deg[dst[e]], 1);
}

__global__ void scan_offsets_kernel() {
    __shared__ int warp_sums[32];
    __shared__ int carry_sh;
    int t = threadIdx.x, lane = t & 31, w = t >> 5;
    if (t == 0) carry_sh = 0;
    __syncthreads();
    for (int base = 0; base < N_NODES; base += 4096) {
        int i4 = base + t * 4;
        int4 v = make_int4(0, 0, 0, 0);
        if (i4 < N_NODES) v = *(const int4*)&g_deg[i4];
        int s0 = v.x, s1 = s0 + v.y, s2 = s1 + v.z, s3 = s2 + v.w;
        int incl = s3;
        #pragma unroll
        for (int off = 1; off < 32; off <<= 1) {
            int x = __shfl_up_sync(0xffffffffu, incl, off);
            if (lane >= off) incl += x;
        }
        if (lane == 31) warp_sums[w] = incl;
        __syncthreads();
        if (w == 0) {
            int s = warp_sums[lane];
            #pragma unroll
            for (int off = 1; off < 32; off <<= 1) {
                int x = __shfl_up_sync(0xffffffffu, s, off);
                if (lane >= off) s += x;
            }
            warp_sums[lane] = s;
        }
        __syncthreads();
        int carry = carry_sh;
        int woff = (w > 0) ? warp_sums[w - 1] : 0;
        int excl = carry + woff + incl - s3;
        if (i4 < N_NODES) {
            *(int4*)&g_off[i4] =
                make_int4(excl, excl + s0, excl + s1, excl + s2);
            *(float4*)&g_invdeg[i4] = make_float4(
                1.0f / (float)max(v.x, 1), 1.0f / (float)max(v.y, 1),
                1.0f / (float)max(v.z, 1), 1.0f / (float)max(v.w, 1));
            *(int4*)&g_cursor[i4] = make_int4(0, 0, 0, 0);
        }
        __syncthreads();
        if (t == 1023) carry_sh = carry + woff + incl;
        __syncthreads();
    }
    if (t == 0) g_off[N_NODES] = carry_sh;
}

__global__ void fill_csr_kernel(const int* __restrict__ src,
                                const int* __restrict__ dst) {
    int e = blockIdx.x * blockDim.x + threadIdx.x;
    if (e < N_EDGES) {
        int d = dst[e];
        int p = atomicAdd(&g_cursor[d], 1);
        g_csr[g_off[d] + p] = src[e];
    }
}

// ---------------- x -> fp16 copy (once) ----------------
__global__ void convert_x_kernel(const float* __restrict__ x) {
    int i = blockIdx.x * blockDim.x + threadIdx.x;
    if (i < N_NODES * D / 4) {
        float4 v = ((const float4*)x)[i];
        __half2* o = (__half2*)g_xf16;
        o[i * 2]     = __floats2half2_rn(v.x, v.y);
        o[i * 2 + 1] = __floats2half2_rn(v.z, v.w);
    }
}

// ---------------- weight prep: fp16, transposed + permuted-K, all layers -----
__global__ void prep_w_kernel(const float* __restrict__ Ws,
                              const float* __restrict__ Wn) {
    int idx = blockIdx.x * blockDim.x + threadIdx.x;
    if (idx >= 3 * 128 * 256) return;
    int l = idx / (128 * 256);
    int rem = idx - l * 128 * 256;
    int n = rem >> 8;
    int k = rem & 255;
    float w = (k < 128) ? __ldg(&Ws[(size_t)l * D * D + k * 128 + n])
                        : __ldg(&Wn[(size_t)l * D * D + (k - 128) * 128 + n]);
    int group = k >> 4, li = k & 15;
    int p = ((li & 7) >> 1) * 4 + (li & 1) + ((li >> 3) << 1);
    g_wt16[l * 128 * KPAD + n * KPAD + group * 16 + p] = __float2half_rn(w);
}

// ---------------- aggregation: one warp per node, fp16 in/out ----------------
__device__ __forceinline__ void acc_h4(float4& a, uint2 r) {
    __half2 p0 = *reinterpret_cast<__half2*>(&r.x);
    __half2 p1 = *reinterpret_cast<__half2*>(&r.y);
    float2 f0 = __half22float2(p0);
    float2 f1 = __half22float2(p1);
    a.x += f0.x; a.y += f0.y; a.z += f1.x; a.w += f1.y;
}

__global__ void __launch_bounds__(256) aggregate_f16_kernel(
    const __half* __restrict__ hin16)
{
    int gw = (blockIdx.x * blockDim.x + threadIdx.x) >> 5;
    int lane = threadIdx.x & 31;
    if (gw >= N_NODES) return;
    int s = g_off[gw], e = g_off[gw + 1];
    const uint2* H = (const uint2*)hin16;   // 4 halves per lane
    float4 a0 = make_float4(0.f, 0.f, 0.f, 0.f);
    float4 a1 = a0, a2 = a0, a3 = a0;
    int j = s;
    for (; j + 4 <= e; j += 4) {
        int u0 = __ldg(&g_csr[j]);
        int u1 = __ldg(&g_csr[j + 1]);
        int u2 = __ldg(&g_csr[j + 2]);
        int u3 = __ldg(&g_csr[j + 3]);
        uint2 r0 = __ldg(&H[(size_t)u0 * 32 + lane]);
        uint2 r1 = __ldg(&H[(size_t)u1 * 32 + lane]);
        uint2 r2 = __ldg(&H[(size_t)u2 * 32 + lane]);
        uint2 r3 = __ldg(&H[(size_t)u3 * 32 + lane]);
        acc_h4(a0, r0); acc_h4(a1, r1); acc_h4(a2, r2); acc_h4(a3, r3);
    }
    for (; j < e; j++) {
        int u = __ldg(&g_csr[j]);
        uint2 r = __ldg(&H[(size_t)u * 32 + lane]);
        acc_h4(a0, r);
    }
    float inv = g_invdeg[gw];
    __half2 o0 = __floats2half2_rn((a0.x + a1.x + a2.x + a3.x) * inv,
                                   (a0.y + a1.y + a2.y + a3.y) * inv);
    __half2 o1 = __floats2half2_rn((a0.z + a1.z + a2.z + a3.z) * inv,
                                   (a0.w + a1.w + a2.w + a3.w) * inv);
    uint2 o;
    o.x = *reinterpret_cast<uint32_t*>(&o0);
    o.y = *reinterpret_cast<uint32_t*>(&o1);
    ((uint2*)g_hn16)[(size_t)gw * 32 + lane] = o;
}

// ---------------- persistent single-product fp16 GEMM (8 warps, 2 CTA/SM) ----
//   C = A * W  (fp32 accum, m16n8k16 f16 mma.sync), A = [h16 | hn16]
#define ABUF (128 * APAD)                          // fp16 units per buffer
#define GEMM_SMEM_BYTES ((128 * KPAD + 2 * ABUF) * 2)   // 88064 B

__device__ __forceinline__ void mma_f16(float c[4], uint32_t a0, uint32_t a1,
                                        uint32_t a2, uint32_t a3,
                                        uint32_t b0, uint32_t b1) {
    asm volatile(
        "mma.sync.aligned.m16n8k16.row.col.f32.f16.f16.f32 "
        "{%0,%1,%2,%3}, {%4,%5,%6,%7}, {%8,%9}, {%0,%1,%2,%3};"
        : "+f"(c[0]), "+f"(c[1]), "+f"(c[2]), "+f"(c[3])
        : "r"(a0), "r"(a1), "r"(a2), "r"(a3), "r"(b0), "r"(b1));
}

__global__ void __launch_bounds__(256, 2) sage_gemm_kernel(
    const __half* __restrict__ h16, const __half* __restrict__ hn16,
    const __half* __restrict__ wt16, const float* __restrict__ bias,
    float* __restrict__ out32, __half* __restrict__ out16)
{
    extern __shared__ __align__(16) __half smem[];
    __half* sW = smem;                    // [128][KPAD]
    __half* sAbuf = sW + 128 * KPAD;      // 2 x [128][APAD]

    int tid = threadIdx.x;
    int lane = tid & 31, warp = tid >> 5;
    int warpM = warp & 3, warpN = warp >> 2;          // 4 x 2 warp grid
    int g = lane >> 2, tig = lane & 3;

    // stage fp16 weights once per CTA (4224 uint4)
    {
        const uint4* s0 = (const uint4*)wt16;
        uint4* d0 = (uint4*)sW;
        for (int i = tid; i < (128 * KPAD) / 8; i += 256)
            d0[i] = s0[i];
    }

    float bx[8], by[8];
    #pragma unroll
    for (int nf = 0; nf < 8; nf++) {
        int col = warpN * 64 + nf * 8 + tig * 2;
        bx[nf] = __ldg(&bias[col]);
        by[nf] = __ldg(&bias[col + 1]);
    }

    const int ptab[4] = {0, 8, 2, 10};

    for (int tile = blockIdx.x; tile < GEMM_TILES; tile += gridDim.x) {
        int m0 = tile * 128;

        float acc[2][8][4];
        #pragma unroll
        for (int mf = 0; mf < 2; mf++)
            #pragma unroll
            for (int nf = 0; nf < 8; nf++)
                #pragma unroll
                for (int r = 0; r < 4; r++) acc[mf][nf][r] = 0.f;

        // preload chunk 0 (self, cols 0..31): 1024 uint2, 4 per thread
        uint2 pref[4];
        #pragma unroll
        for (int i = 0; i < 4; i++) {
            int idx = tid + 256 * i;
            int r = idx >> 3, c4 = idx & 7;
            int m = m0 + r;
            pref[i] = make_uint2(0u, 0u);
            if (m < N_NODES)
                pref[i] = __ldg((const uint2*)(h16 + (size_t)m * D + c4 * 4));
        }

        #pragma unroll 1
        for (int kc = 0; kc < 8; kc++) {
            __half* sA = sAbuf + (kc & 1) * ABUF;

            // store prefetched fp16 into permuted-K smem
            #pragma unroll
            for (int i = 0; i < 4; i++) {
                int idx = tid + 256 * i;
                int r = idx >> 3, c4 = idx & 7;
                int group = c4 >> 2;
                int p0 = ptab[c4 & 3];
                int base = r * APAD + group * 16;
                uint32_t* A32 = (uint32_t*)sA;
                A32[(base + p0) >> 1]     = pref[i].x;
                A32[(base + p0 + 4) >> 1] = pref[i].y;
            }
            __syncthreads();   // first iteration also covers W staging

            if (kc < 7) {
                int nkc = kc + 1;
                const __half* srcp = (nkc < 4) ? h16 : hn16;
                int koff = (nkc & 3) * 32;
                #pragma unroll
                for (int i = 0; i < 4; i++) {
                    int idx = tid + 256 * i;
                    int r = idx >> 3, c4 = idx & 7;
                    int m = m0 + r;
                    pref[i] = make_uint2(0u, 0u);
                    if (m < N_NODES)
                        pref[i] = __ldg((const uint2*)(srcp + (size_t)m * D +
                                                       koff + c4 * 4));
                }
            }

            #pragma unroll
            for (int ks = 0; ks < 2; ks++) {
                int ka = ks * 16;
                int kw = kc * 32 + ks * 16;
                uint32_t A[2][4];
                #pragma unroll
                for (int mf = 0; mf < 2; mf++) {
                    int r0 = warpM * 32 + mf * 16;
                    uint2 t0 = *(const uint2*)&sA[(r0 + g) * APAD + ka + tig * 4];
                    uint2 t1 = *(const uint2*)&sA[(r0 + g + 8) * APAD + ka + tig * 4];
                    A[mf][0] = t0.x; A[mf][1] = t1.x; A[mf][2] = t0.y; A[mf][3] = t1.y;
                }
                #pragma unroll
                for (int nf = 0; nf < 8; nf++) {
                    int nr = warpN * 64 + nf * 8 + g;
                    uint2 b = *(const uint2*)&sW[nr * KPAD + kw + tig * 4];
                    #pragma unroll
                    for (int mf = 0; mf < 2; mf++)
                        mma_f16(acc[mf][nf], A[mf][0], A[mf][1], A[mf][2], A[mf][3],
                                b.x, b.y);
                }
            }
        }

        // epilogue: + bias, relu; fp16 store (hidden layers) or fp32 (last)
        #pragma unroll
        for (int mf = 0; mf < 2; mf++) {
            #pragma unroll
            for (int nf = 0; nf < 8; nf++) {
                int row0 = m0 + warpM * 32 + mf * 16 + g;
                int col = warpN * 64 + nf * 8 + tig * 2;
                float r0 = acc[mf][nf][0] + bx[nf]; r0 = r0 > 0.f ? r0 : 0.f;
                float r1 = acc[mf][nf][1] + by[nf]; r1 = r1 > 0.f ? r1 : 0.f;
                float r2 = acc[mf][nf][2] + bx[nf]; r2 = r2 > 0.f ? r2 : 0.f;
                float r3 = acc[mf][nf][3] + by[nf]; r3 = r3 > 0.f ? r3 : 0.f;
                if (row0 < N_NODES) {
                    if (out32) *(float2*)&out32[(size_t)row0 * D + col] =
                        make_float2(r0, r1);
                    if (out16) *(__half2*)&out16[(size_t)row0 * D + col] =
                        __floats2half2_rn(r0, r1);
                }
                if (row0 + 8 < N_NODES) {
                    if (out32) *(float2*)&out32[(size_t)(row0 + 8) * D + col] =
                        make_float2(r2, r3);
                    if (out16) *(__half2*)&out16[(size_t)(row0 + 8) * D + col] =
                        __floats2half2_rn(r2, r3);
                }
            }
        }
        __syncthreads();   // A buffers reused next tile
    }
}

// ---------------- launch ----------------
extern "C" void kernel_launch(void* const* d_in, const int* in_sizes, int n_in,
                              void* d_out, int out_size)
{
    const float* x       = (const float*)d_in[0];
    const float* W_self  = (const float*)d_in[1];
    const float* W_neigh = (const float*)d_in[2];
    const float* bias    = (const float*)d_in[3];
    const int*   src     = (const int*)d_in[4];
    const int*   dst     = (const int*)d_in[5];
    float* out = (float*)d_out;

    void *px16, *pa16, *pb16, *pn16, *pw;
    cudaGetSymbolAddress(&px16, g_xf16);
    cudaGetSymbolAddress(&pa16, g_hf16a);
    cudaGetSymbolAddress(&pb16, g_hf16b);
    cudaGetSymbolAddress(&pn16, g_hn16);
    cudaGetSymbolAddress(&pw, g_wt16);
    __half* x16 = (__half*)px16;
    __half* a16 = (__half*)pa16;
    __half* b16 = (__half*)pb16;
    __half* hn16 = (__half*)pn16;
    const __half* wt16 = (const __half*)pw;

    static cudaStream_t s2 = nullptr;
    static cudaEvent_t evFork, evPrep;
    if (s2 == nullptr) {
        cudaStreamCreateWithFlags(&s2, cudaStreamNonBlocking);
        cudaEventCreateWithFlags(&evFork, cudaEventDisableTiming);
        cudaEventCreateWithFlags(&evPrep, cudaEventDisableTiming);
        cudaFuncSetAttribute(sage_gemm_kernel,
                             cudaFuncAttributeMaxDynamicSharedMemorySize,
                             GEMM_SMEM_BYTES);
    }

    // fork: convert x -> fp16 and prep all weights, concurrent with CSR build
    cudaEventRecord(evFork, 0);
    cudaStreamWaitEvent(s2, evFork, 0);
    convert_x_kernel<<<(N_NODES * D / 4 + 255) / 256, 256, 0, s2>>>(x);
    prep_w_kernel<<<(3 * 128 * 256 + 255) / 256, 256, 0, s2>>>(W_self, W_neigh);
    cudaEventRecord(evPrep, s2);

    zero_deg_kernel<<<(N_NODES + 255) / 256, 256>>>();
    count_deg_kernel<<<(N_EDGES + 255) / 256, 256>>>(dst);
    scan_offsets_kernel<<<1, 1024>>>();
    fill_csr_kernel<<<(N_EDGES + 255) / 256, 256>>>(src, dst);
    cudaStreamWaitEvent(0, evPrep, 0);    // join: agg needs x16, gemm needs W

    const __half* hin16 = x16;
    __half* houts16[3] = {a16, b16, nullptr};
    float* houts32[3] = {nullptr, nullptr, out};
    for (int l = 0; l < L_LAYERS; l++) {
        aggregate_f16_kernel<<<(N_NODES + 7) / 8, 256>>>(hin16);
        sage_gemm_kernel<<<GEMM_GRID, 256, GEMM_SMEM_BYTES>>>(
            hin16, hn16, wt16 + (size_t)l * 128 * KPAD,
            bias + (size_t)l * D, houts32[l], houts16[l]);
        hin16 = houts16[l];
    }
}